// round 9
// baseline (speedup 1.0000x reference)
#include <cuda_runtime.h>
#include <cstdint>

#define CDIM 256
#define NDIM 512
#define TM   32
#define NTH  256
#define MF   8
#define KC   16
#define KITER 15

typedef unsigned long long u64;

// Scratch (device-global: allocation-free)
__device__ float g_Ws[NDIM * NDIM];     // symmetrized W
__device__ float g_WinT[CDIM * NDIM];   // W_in^T  (256 x 512)
__device__ float g_WoutT[NDIM * CDIM];  // W_out^T (512 x 256)

// ---------- packed f32x2 helpers ----------
__device__ __forceinline__ u64 pack2(float lo, float hi) {
    u64 r; asm("mov.b64 %0,{%1,%2};" : "=l"(r) : "f"(lo), "f"(hi)); return r;
}
__device__ __forceinline__ float2 unpack2(u64 v) {
    float2 f; asm("mov.b64 {%0,%1},%2;" : "=f"(f.x), "=f"(f.y) : "l"(v)); return f;
}
__device__ __forceinline__ u64 fma2(u64 a, u64 b, u64 c) {
    u64 d; asm("fma.rn.f32x2 %0,%1,%2,%3;" : "=l"(d) : "l"(a), "l"(b), "l"(c)); return d;
}
__device__ __forceinline__ u64 add2(u64 a, u64 b) {
    u64 d; asm("add.rn.f32x2 %0,%1,%2;" : "=l"(d) : "l"(a), "l"(b)); return d;
}
__device__ __forceinline__ float tanh_fast(float v) {
    float r; asm("tanh.approx.f32 %0,%1;" : "=f"(r) : "f"(v)); return r;
}
__device__ __forceinline__ float tanh_accurate(float v) {
    float e = __expf(2.0f * v);
    return 1.0f - 2.0f / (e + 1.0f);
}

// ---------- cp.async helpers ----------
__device__ __forceinline__ void cpa16(uint32_t d, const void* s) {
    asm volatile("cp.async.cg.shared.global [%0], [%1], 16;" :: "r"(d), "l"(s));
}
__device__ __forceinline__ void cp_commit() { asm volatile("cp.async.commit_group;" ::); }
__device__ __forceinline__ void cp_wait0()  { asm volatile("cp.async.wait_group 0;" ::); }
__device__ __forceinline__ void cp_wait1()  { asm volatile("cp.async.wait_group 1;" ::); }

template <int BYTES>
__device__ __forceinline__ void copy_chunk(float* dst, const float* src) {
    uint32_t d = (uint32_t)__cvta_generic_to_shared(dst) + threadIdx.x * 16;
    const char* s = (const char*)src + threadIdx.x * 16;
#pragma unroll
    for (int off = 0; off < BYTES; off += NTH * 16)
        cpa16(d + off, s + off);
}

// ---------- inner GEMM chunk: acc[m][n-pairs] += a[m][k] * w[k][n] ----------
template <int ASTRIDE, int WSTRIDE, int NJ>
__device__ __forceinline__ void gemm_chunk(const float* __restrict__ a_sm, int m0, int kbase,
                                           const float* __restrict__ wch, int n0,
                                           u64 (&acc)[MF][NJ]) {
#pragma unroll
    for (int k = 0; k < KC; k++) {
        float av[MF];
#pragma unroll
        for (int i = 0; i < MF; i++) av[i] = a_sm[(m0 + i) * ASTRIDE + kbase + k];
        u64 w[NJ];
#pragma unroll
        for (int jj = 0; jj < NJ / 2; jj++) {
            ulonglong2 tv = *(const ulonglong2*)(wch + k * WSTRIDE + n0 + jj * 4);
            w[2 * jj] = tv.x; w[2 * jj + 1] = tv.y;
        }
#pragma unroll
        for (int i = 0; i < MF; i++) {
            u64 aa = pack2(av[i], av[i]);
#pragma unroll
            for (int j = 0; j < NJ; j++) acc[i][j] = fma2(aa, w[j], acc[i][j]);
        }
    }
}

// ---------- prep: symmetrize W, transpose W_in / W_out ----------
__global__ void prep_kernel(const float* __restrict__ W_in,
                            const float* __restrict__ W,
                            const float* __restrict__ W_out) {
    int i = blockIdx.x * blockDim.x + threadIdx.x;
    if (i < NDIM * NDIM) {
        int r = i >> 9, c = i & 511;
        g_Ws[i] = 0.5f * (W[i] + W[c * NDIM + r]);
    }
    if (i < CDIM * NDIM) {
        int k = i >> 9, n = i & 511;
        g_WinT[i] = W_in[n * CDIM + k];
    }
    if (i < NDIM * CDIM) {
        int n = i >> 8, j = i & 255;
        g_WoutT[i] = W_out[j * NDIM + n];
    }
}

// ---------- fused attractor kernel ----------
__global__ void __launch_bounds__(NTH, 1)
attractor_kernel(const float* __restrict__ x, const float* __restrict__ b_in,
                 const float* __restrict__ bvec, const float* __restrict__ b_out,
                 float* __restrict__ y) {
    extern __shared__ float smem[];
    float* a_sm = smem;  // TM x NDIM
    float* wb[3];
    wb[0] = smem + TM * NDIM;
    wb[1] = wb[0] + KC * NDIM;
    wb[2] = wb[1] + KC * NDIM;

    const int tid = threadIdx.x;
    const int tn = tid & 63;   // col group (64)
    const int tm = tid >> 6;   // row group (4)
    const int m0 = tm * MF;
    const int n0 = tn * 8;
    const long row0 = (long)blockIdx.x * TM;

    u64 acc[MF][4];
    u64 ceff[MF][4];

    // ===== Phase A: c = x @ W_in^T  (x tile staged at stride NDIM) =====
    {
        uint32_t base = (uint32_t)__cvta_generic_to_shared(a_sm);
        const char* xs = (const char*)(x + row0 * CDIM);
#pragma unroll
        for (int it = 0; it < (TM * CDIM * 4) / (NTH * 16); it++) {  // 8
            int idx = it * NTH + tid;           // 16B unit, 0..2047
            int r = idx >> 6;                   // row (64 units of 16B per row)
            int o = (idx & 63) * 16;
            cpa16(base + r * NDIM * 4 + o, xs + r * CDIM * 4 + o);
        }
        cp_commit();
    }
    copy_chunk<KC * NDIM * 4>(wb[0], g_WinT); cp_commit();
    copy_chunk<KC * NDIM * 4>(wb[1], g_WinT + KC * NDIM); cp_commit();

#pragma unroll
    for (int i = 0; i < MF; i++)
#pragma unroll
        for (int j = 0; j < 4; j++) acc[i][j] = 0ull;

#pragma unroll 1
    for (int kc = 0; kc < 16; kc++) {  // 256 / KC
        if (kc == 15) cp_wait0(); else cp_wait1();
        __syncthreads();
        if (kc + 2 < 16) { copy_chunk<KC * NDIM * 4>(wb[(kc + 2) % 3], g_WinT + (kc + 2) * KC * NDIM); cp_commit(); }
        gemm_chunk<NDIM, NDIM, 4>(a_sm, m0, kc * KC, wb[kc % 3], n0, acc);
    }
    __syncthreads();

    // fold biases: ceff = c + b_in + b   (iteration adds b + c every step)
    {
        float4 bi0 = *(const float4*)(b_in + n0);
        float4 bi1 = *(const float4*)(b_in + n0 + 4);
        float4 bv0 = *(const float4*)(bvec + n0);
        float4 bv1 = *(const float4*)(bvec + n0 + 4);
        u64 bb[4] = { pack2(bi0.x + bv0.x, bi0.y + bv0.y), pack2(bi0.z + bv0.z, bi0.w + bv0.w),
                      pack2(bi1.x + bv1.x, bi1.y + bv1.y), pack2(bi1.z + bv1.z, bi1.w + bv1.w) };
#pragma unroll
        for (int i = 0; i < MF; i++)
#pragma unroll
            for (int j = 0; j < 4; j++) ceff[i][j] = add2(acc[i][j], bb[j]);
    }

    // ===== iteration 1: a1 = tanh(ceff) (a0 = 0, GEMM skipped) =====
#pragma unroll
    for (int i = 0; i < MF; i++) {
        float v[8];
#pragma unroll
        for (int j = 0; j < 4; j++) {
            float2 f = unpack2(ceff[i][j]);
            v[2 * j] = tanh_fast(f.x); v[2 * j + 1] = tanh_fast(f.y);
        }
        *(float4*)(a_sm + (m0 + i) * NDIM + n0)     = make_float4(v[0], v[1], v[2], v[3]);
        *(float4*)(a_sm + (m0 + i) * NDIM + n0 + 4) = make_float4(v[4], v[5], v[6], v[7]);
    }

    // ===== iterations 2..15: a = tanh(a @ Ws + ceff) =====
#pragma unroll 1
    for (int t = 0; t < KITER - 1; t++) {
        const bool last = (t == KITER - 2);
#pragma unroll
        for (int i = 0; i < MF; i++)
#pragma unroll
            for (int j = 0; j < 4; j++) acc[i][j] = ceff[i][j];

        copy_chunk<KC * NDIM * 4>(wb[0], g_Ws); cp_commit();
        copy_chunk<KC * NDIM * 4>(wb[1], g_Ws + KC * NDIM); cp_commit();
#pragma unroll 1
        for (int kc = 0; kc < 32; kc++) {  // 512 / KC
            if (kc == 31) cp_wait0(); else cp_wait1();
            __syncthreads();
            if (kc + 2 < 32) { copy_chunk<KC * NDIM * 4>(wb[(kc + 2) % 3], g_Ws + (kc + 2) * KC * NDIM); cp_commit(); }
            gemm_chunk<NDIM, NDIM, 4>(a_sm, m0, kc * KC, wb[kc % 3], n0, acc);
        }
        __syncthreads();  // all reads of a_sm done before overwrite

#pragma unroll
        for (int i = 0; i < MF; i++) {
            float v[8];
#pragma unroll
            for (int j = 0; j < 4; j++) {
                float2 f = unpack2(acc[i][j]);
                if (last) { v[2 * j] = tanh_accurate(f.x); v[2 * j + 1] = tanh_accurate(f.y); }
                else      { v[2 * j] = tanh_fast(f.x);     v[2 * j + 1] = tanh_fast(f.y); }
            }
            *(float4*)(a_sm + (m0 + i) * NDIM + n0)     = make_float4(v[0], v[1], v[2], v[3]);
            *(float4*)(a_sm + (m0 + i) * NDIM + n0 + 4) = make_float4(v[4], v[5], v[6], v[7]);
        }
    }

    // ===== Phase C: y = a @ W_out^T + b_out =====
    {
        const int j0 = tn * 4;
        u64 oacc[MF][2];
        float4 bo = *(const float4*)(b_out + j0);
#pragma unroll
        for (int i = 0; i < MF; i++) { oacc[i][0] = pack2(bo.x, bo.y); oacc[i][1] = pack2(bo.z, bo.w); }

        copy_chunk<KC * CDIM * 4>(wb[0], g_WoutT); cp_commit();
        copy_chunk<KC * CDIM * 4>(wb[1], g_WoutT + KC * CDIM); cp_commit();
#pragma unroll 1
        for (int nc = 0; nc < 32; nc++) {  // 512 / KC
            if (nc == 31) cp_wait0(); else cp_wait1();
            __syncthreads();
            if (nc + 2 < 32) { copy_chunk<KC * CDIM * 4>(wb[(nc + 2) % 3], g_WoutT + (nc + 2) * KC * CDIM); cp_commit(); }
            gemm_chunk<NDIM, CDIM, 2>(a_sm, m0, nc * KC, wb[nc % 3], j0, oacc);
        }

#pragma unroll
        for (int i = 0; i < MF; i++) {
            float2 p0 = unpack2(oacc[i][0]);
            float2 p1 = unpack2(oacc[i][1]);
            *(float4*)(y + (row0 + m0 + i) * CDIM + j0) = make_float4(p0.x, p0.y, p1.x, p1.y);
        }
    }
}

extern "C" void kernel_launch(void* const* d_in, const int* in_sizes, int n_in,
                              void* d_out, int out_size) {
    const float* x     = (const float*)d_in[0];
    const float* W_in  = (const float*)d_in[1];
    const float* b_in  = (const float*)d_in[2];
    const float* W     = (const float*)d_in[3];
    const float* bvec  = (const float*)d_in[4];
    const float* W_out = (const float*)d_in[5];
    const float* b_out = (const float*)d_in[6];
    float* y = (float*)d_out;

    const int rows = in_sizes[0] / CDIM;       // 65536
    const int nblk = rows / TM;                // 2048
    const int smem_bytes = (TM * NDIM + 3 * KC * NDIM) * 4;  // 64KB + 96KB = 160KB

    cudaFuncSetAttribute(attractor_kernel,
                         cudaFuncAttributeMaxDynamicSharedMemorySize, smem_bytes);

    prep_kernel<<<1024, 256>>>(W_in, W, W_out);
    attractor_kernel<<<nblk, NTH, smem_bytes>>>(x, b_in, bvec, b_out, y);
}

// round 10
// speedup vs baseline: 1.2208x; 1.2208x over previous
#include <cuda_runtime.h>
#include <cstdint>

#define CDIM 256
#define NDIM 512
#define TM   32
#define NTH  256
#define KITER 15
#define ATS  36                    // a_t padded stride (floats), 16B-aligned rows
#define ATFLOATS (NDIM * ATS)      // 18432 floats = 73728 B
#define RINGF_PER_WARP 4096        // floats: 4 chunks x 8 k x 128 floats = 16KB

typedef unsigned long long u64;

// Device-global scratch (allocation-free), value-duplicated weight layouts.
__device__ float g_Wsd[NDIM * 2 * NDIM];     // [k=512][1024]  dup symmetrized W
__device__ float g_WinTd[CDIM * 2 * NDIM];   // [k=256][1024]  dup W_in^T
__device__ float g_WoutTd[NDIM * 2 * CDIM];  // [k=512][512]   dup W_out^T

// ---------- packed f32x2 helpers ----------
__device__ __forceinline__ u64 pack2(float lo, float hi) {
    u64 r; asm("mov.b64 %0,{%1,%2};" : "=l"(r) : "f"(lo), "f"(hi)); return r;
}
__device__ __forceinline__ float2 unpack2(u64 v) {
    float2 f; asm("mov.b64 {%0,%1},%2;" : "=f"(f.x), "=f"(f.y) : "l"(v)); return f;
}
__device__ __forceinline__ u64 fma2(u64 a, u64 b, u64 c) {
    u64 d; asm("fma.rn.f32x2 %0,%1,%2,%3;" : "=l"(d) : "l"(a), "l"(b), "l"(c)); return d;
}
__device__ __forceinline__ u64 add2(u64 a, u64 b) {
    u64 d; asm("add.rn.f32x2 %0,%1,%2;" : "=l"(d) : "l"(a), "l"(b)); return d;
}
__device__ __forceinline__ float tanh_fast(float v) {
    float r; asm("tanh.approx.f32 %0,%1;" : "=f"(r) : "f"(v)); return r;
}
__device__ __forceinline__ float tanh_accurate(float v) {
    float e = __expf(2.0f * v);
    return 1.0f - 2.0f / (e + 1.0f);
}

// ---------- cp.async helpers ----------
__device__ __forceinline__ void cpa16(uint32_t d, const void* s) {
    asm volatile("cp.async.cg.shared.global [%0], [%1], 16;" :: "r"(d), "l"(s));
}
__device__ __forceinline__ void cp_commit() { asm volatile("cp.async.commit_group;" ::); }

// ---------- per-warp streaming GEMM over a private cp.async ring ----------
// acc[p][c]: row-pair p (rows 2p,2p+1) packed in f32x2, c = lane-local column.
// gw: this warp's slice start in the dup weight matrix (row stride ROWF floats).
template <int K, int SLICEF, int NC, int ROWF>
__device__ __forceinline__ void stream_gemm(const float* __restrict__ gw,
                                            const float* __restrict__ a_t,
                                            float* __restrict__ ringw,
                                            int lane, u64 (&acc)[16][NC]) {
    constexpr int UPK  = SLICEF / 4;   // 16B units per k-slice (32 or 16)
    constexpr int NCPA = SLICEF / 16;  // cpa16 per lane per 8-k chunk (8 or 4)
    constexpr int NCH  = K / 8;
    uint32_t rbase = (uint32_t)__cvta_generic_to_shared(ringw);

    auto issue = [&](int ch) {
        int k0 = ch * 8, slot = ch & 3;
#pragma unroll
        for (int q = 0; q < NCPA; q++) {
            int i  = q * 32 + lane;
            int ko = i / UPK, uo = i % UPK;
            cpa16(rbase + (((slot * 8 + ko) * SLICEF) + uo * 4) * 4,
                  gw + (long)(k0 + ko) * ROWF + uo * 4);
        }
    };
    issue(0); cp_commit();
    issue(1); cp_commit();
    issue(2); cp_commit();

#pragma unroll 1
    for (int ch = 0; ch < NCH; ch++) {
        if (ch + 3 < NCH) issue(ch + 3);
        cp_commit();                              // possibly-empty group keeps counting simple
        asm volatile("cp.async.wait_group 3;" ::);
        __syncwarp();
        const float* wch = ringw + (ch & 3) * 8 * SLICEF;
#pragma unroll
        for (int kk = 0; kk < 8; kk++) {
            int k = ch * 8 + kk;
            const ulonglong2* ap = (const ulonglong2*)(a_t + k * ATS);
            u64 a8[16];
#pragma unroll
            for (int q = 0; q < 8; q++) { ulonglong2 t = ap[q]; a8[2*q] = t.x; a8[2*q+1] = t.y; }
            if (NC == 2) {
                ulonglong2 wv = *(const ulonglong2*)(wch + kk * SLICEF + lane * 4);
#pragma unroll
                for (int p = 0; p < 16; p++) {
                    acc[p][0] = fma2(a8[p], wv.x, acc[p][0]);
                    acc[p][NC - 1] = fma2(a8[p], wv.y, acc[p][NC - 1]);
                }
            } else {
                u64 wv = *(const u64*)(wch + kk * SLICEF + lane * 2);
#pragma unroll
                for (int p = 0; p < 16; p++) acc[p][0] = fma2(a8[p], wv, acc[p][0]);
            }
        }
    }
}

// ---------- prep: build duplicated weight layouts ----------
__global__ void prep_kernel(const float* __restrict__ W_in,
                            const float* __restrict__ W,
                            const float* __restrict__ W_out) {
    int i = blockIdx.x * blockDim.x + threadIdx.x;
    if (i < NDIM * NDIM) {                       // Ws dup: [k][2n]=[k][2n+1]=0.5(W[k][n]+W[n][k])
        int k = i >> 9, n = i & 511;
        float v = 0.5f * (W[i] + W[n * NDIM + k]);
        g_Wsd[k * 1024 + 2 * n] = v; g_Wsd[k * 1024 + 2 * n + 1] = v;
    }
    if (i < CDIM * NDIM) {                       // W_in^T dup: [k][2n(+1)] = W_in[n][k]
        int k = i >> 9, n = i & 511;
        float v = W_in[n * CDIM + k];
        g_WinTd[k * 1024 + 2 * n] = v; g_WinTd[k * 1024 + 2 * n + 1] = v;
    }
    if (i < NDIM * CDIM) {                       // W_out^T dup: [k][2j(+1)] = W_out[j][k]
        int k = i >> 8, j = i & 255;
        float v = W_out[j * NDIM + k];
        g_WoutTd[k * 512 + 2 * j] = v; g_WoutTd[k * 512 + 2 * j + 1] = v;
    }
}

// ---------- fused attractor kernel ----------
__global__ void __launch_bounds__(NTH, 1)
attractor_kernel(const float* __restrict__ x, const float* __restrict__ b_in,
                 const float* __restrict__ bvec, const float* __restrict__ b_out,
                 float* __restrict__ y) {
    extern __shared__ float smem[];
    float* a_t   = smem;                       // [512 k][32 rows] stride ATS
    float* ringf = smem + ATFLOATS;            // per-warp cp.async rings

    const int tid  = threadIdx.x;
    const int wid  = tid >> 5;
    const int lane = tid & 31;
    float* ringw = ringf + wid * RINGF_PER_WARP;
    const long row0 = (long)blockIdx.x * TM;

    // ===== stage x transposed into a_t (k = channel, first 256 rows) =====
#pragma unroll 4
    for (int r = 0; r < TM; r++)
        a_t[tid * ATS + r] = x[(row0 + r) * CDIM + tid];   // coalesced LDG, tid = channel
    __syncthreads();

    // ===== Phase A: c = x @ W_in^T  (K=256) =====
    u64 acc[16][2], ceff[16][2];
#pragma unroll
    for (int p = 0; p < 16; p++) { acc[p][0] = 0ull; acc[p][1] = 0ull; }
    stream_gemm<CDIM, 128, 2, 1024>(g_WinTd + wid * 128, a_t, ringw, lane, acc);

    // ceff = c + b_in + b  (per lane: cols c0, c0+1; bias same across the row-pair halves)
    const int c0 = 64 * wid + 2 * lane;
    {
        u64 bb0 = pack2(b_in[c0] + bvec[c0], b_in[c0] + bvec[c0]);
        u64 bb1 = pack2(b_in[c0 + 1] + bvec[c0 + 1], b_in[c0 + 1] + bvec[c0 + 1]);
#pragma unroll
        for (int p = 0; p < 16; p++) {
            ceff[p][0] = add2(acc[p][0], bb0);
            ceff[p][1] = add2(acc[p][1], bb1);
        }
    }

    // ===== iteration 1: a1 = tanh(ceff)  (a0 = 0, GEMM skipped) =====
    __syncthreads();   // all warps done reading x_t
#pragma unroll
    for (int c = 0; c < 2; c++) {
        float v[32];
#pragma unroll
        for (int p = 0; p < 16; p++) {
            float2 f = unpack2(ceff[p][c]);
            v[2 * p] = tanh_fast(f.x); v[2 * p + 1] = tanh_fast(f.y);
        }
        float* dst = a_t + (c0 + c) * ATS;
#pragma unroll
        for (int q = 0; q < 8; q++)
            *(float4*)(dst + 4 * q) = make_float4(v[4*q], v[4*q+1], v[4*q+2], v[4*q+3]);
    }
    __syncthreads();

    // ===== iterations 2..15: a = tanh(a @ Ws + ceff) =====
#pragma unroll 1
    for (int t = 0; t < KITER - 1; t++) {
        const bool last = (t == KITER - 2);
#pragma unroll
        for (int p = 0; p < 16; p++) { acc[p][0] = ceff[p][0]; acc[p][1] = ceff[p][1]; }

        stream_gemm<NDIM, 128, 2, 1024>(g_Wsd + wid * 128, a_t, ringw, lane, acc);

        __syncthreads();   // all warps done reading a_t
#pragma unroll
        for (int c = 0; c < 2; c++) {
            float v[32];
#pragma unroll
            for (int p = 0; p < 16; p++) {
                float2 f = unpack2(acc[p][c]);
                if (last) { v[2*p] = tanh_accurate(f.x); v[2*p+1] = tanh_accurate(f.y); }
                else      { v[2*p] = tanh_fast(f.x);     v[2*p+1] = tanh_fast(f.y); }
            }
            float* dst = a_t + (c0 + c) * ATS;
#pragma unroll
            for (int q = 0; q < 8; q++)
                *(float4*)(dst + 4 * q) = make_float4(v[4*q], v[4*q+1], v[4*q+2], v[4*q+3]);
        }
        __syncthreads();
    }

    // ===== Phase C: y = a @ W_out^T + b_out  (1 output col per lane) =====
    {
        const int col = 32 * wid + lane;
        u64 oacc[16][1];
        float bo = b_out[col];
#pragma unroll
        for (int p = 0; p < 16; p++) oacc[p][0] = pack2(bo, bo);

        stream_gemm<NDIM, 64, 1, 512>(g_WoutTd + wid * 64, a_t, ringw, lane, oacc);

        __syncthreads();   // all warps done reading a_t; reuse it as y_t staging
#pragma unroll
        for (int p = 0; p < 16; p++)
            *(u64*)(a_t + col * ATS + 2 * p) = oacc[p][0];   // y_t[col][2p..2p+1]
        __syncthreads();

        // coalesced writeback: thread tid = output channel
#pragma unroll 4
        for (int r = 0; r < TM; r++)
            y[(row0 + r) * CDIM + tid] = a_t[tid * ATS + r];
    }
}

extern "C" void kernel_launch(void* const* d_in, const int* in_sizes, int n_in,
                              void* d_out, int out_size) {
    const float* x     = (const float*)d_in[0];
    const float* W_in  = (const float*)d_in[1];
    const float* b_in  = (const float*)d_in[2];
    const float* W     = (const float*)d_in[3];
    const float* bvec  = (const float*)d_in[4];
    const float* W_out = (const float*)d_in[5];
    const float* b_out = (const float*)d_in[6];
    float* y = (float*)d_out;

    const int rows = in_sizes[0] / CDIM;            // 65536
    const int nblk = rows / TM;                     // 2048
    const int smem_bytes = ATFLOATS * 4 + 8 * RINGF_PER_WARP * 4;  // 73728 + 131072 = 204800

    cudaFuncSetAttribute(attractor_kernel,
                         cudaFuncAttributeMaxDynamicSharedMemorySize, smem_bytes);

    prep_kernel<<<1024, 256>>>(W_in, W, W_out);
    attractor_kernel<<<nblk, NTH, smem_bytes>>>(x, b_in, bvec, b_out, y);
}